// round 1
// baseline (speedup 1.0000x reference)
#include <cuda_runtime.h>
#include <cuda_bf16.h>
#include <math.h>

// ---------------------------------------------------------------------------
// Problem constants
//   x: (16, 1, 1022, 1022) fp32
//   spdconv -> (16,1,511,511), zero-pad to 512x512, rfft2, split into 4 planes
//   of 256x256, 3x3 conv + bias, cumprod over batch, 1x1 fuse, bn+silu,
//   bn+relu, broadcast by w_final[64].
//   softmax over the singleton K*K axis == 1, so the "gw" branch is dead.
// ---------------------------------------------------------------------------

#define NB   16
#define XW   1022
#define NP   512       // padded FFT size
#define HH   256       // half = output spatial size

// Scratch (device globals -- allocation-free)
static __device__ float  g_ypad[(size_t)NB * NP * NP];         // 16.8 MB
static __device__ float2 g_F1[(size_t)NB * NP * HH];           // 16.8 MB (row-FFT, cols 0..255)
static __device__ float  g_planes[(size_t)4 * NB * HH * HH];   // 16.8 MB
static __device__ float2 g_tw[256];                            // twiddles e^{-2pi i k/512}

// ---------------------------------------------------------------------------
__global__ void k_twiddle() {
    int k = threadIdx.x;           // 256 threads
    float s, c;
    sincospif(-(float)k / 256.0f, &s, &c);   // angle = -2*pi*k/512 = -pi*(k/256)
    g_tw[k] = make_float2(c, s);
}

// ---------------------------------------------------------------------------
// Kernel 1: space-to-depth + 1x1 conv + BN + SiLU, written zero-padded to 512x512
__global__ void k_spd(const float* __restrict__ x,
                      const float* __restrict__ w4,
                      const float* __restrict__ bng,
                      const float* __restrict__ bnb) {
    int i = blockIdx.x;            // padded row 0..511
    int b = blockIdx.y;
    int t = threadIdx.x;           // 256
    float w0 = w4[0], w1 = w4[1], w2 = w4[2], w3 = w4[3];
    float sc = bng[0] * rsqrtf(1.0f + 1e-5f);
    float bi = bnb[0];
    const float* xb = x + (size_t)b * XW * XW;
    float* yrow = g_ypad + ((size_t)b * NP + i) * NP;
#pragma unroll
    for (int jj = 0; jj < 2; jj++) {
        int j = t + jj * 256;
        float v = 0.0f;
        if (i < 511 && j < 511) {
            const float* p0 = xb + (size_t)(2 * i) * XW + 2 * j;
            float2 a  = *(const float2*)p0;          // x[2i,2j], x[2i,2j+1]
            float2 c2 = *(const float2*)(p0 + XW);   // x[2i+1,2j], x[2i+1,2j+1]
            float z = w0 * a.x + w1 * c2.x + w2 * a.y + w3 * c2.y;
            z = sc * z + bi;
            v = z / (1.0f + expf(-z));               // SiLU
        }
        yrow[j] = v;
    }
}

// ---------------------------------------------------------------------------
// In-place radix-2 DIT FFT, N=512, 256 threads (one butterfly each per stage).
// Input must be loaded in bit-reversed order. Forward transform (e^{-i...}).
__device__ __forceinline__ float2 cadd(float2 a, float2 b) { return make_float2(a.x + b.x, a.y + b.y); }
__device__ __forceinline__ float2 csub(float2 a, float2 b) { return make_float2(a.x - b.x, a.y - b.y); }
__device__ __forceinline__ float2 cmul(float2 a, float2 b) {
    return make_float2(a.x * b.x - a.y * b.y, a.x * b.y + a.y * b.x);
}

// Kernel 2: row real-FFT, two rows packed as one complex 512-pt FFT.
// Writes F1[b][r][k] (k = 0..255 only, all we ever need), coalesced.
__global__ void k_rowfft() {
    __shared__ float2 s[NP];
    int rp = blockIdx.x;           // row pair 0..255
    int b  = blockIdx.y;
    int t  = threadIdx.x;          // 256
    const float* r0 = g_ypad + ((size_t)b * NP + 2 * rp) * NP;
    const float* r1 = r0 + NP;
    s[__brev(t) >> 23]         = make_float2(r0[t],       r1[t]);
    s[__brev(t + 256) >> 23]   = make_float2(r0[t + 256], r1[t + 256]);
    __syncthreads();
#pragma unroll
    for (int st = 0; st < 9; st++) {
        int half = 1 << st;
        int pos  = t & (half - 1);
        int i0   = ((t >> st) << (st + 1)) | pos;
        int i1   = i0 + half;
        float2 w = g_tw[pos << (8 - st)];
        float2 u = s[i0], v = s[i1];
        float2 wv = cmul(w, v);
        s[i0] = cadd(u, wv);
        s[i1] = csub(u, wv);
        __syncthreads();
    }
    // Unpack the two real spectra (need k = 0..255 only)
    int k = t;
    float2 Fk = s[k];
    float2 Fn = s[(NP - k) & (NP - 1)];
    float2 E = make_float2(0.5f * (Fk.x + Fn.x), 0.5f * (Fk.y - Fn.y));  // row 2rp
    float2 D = make_float2(0.5f * (Fk.x - Fn.x), 0.5f * (Fk.y + Fn.y));
    float2 O = make_float2(D.y, -D.x);                                   // row 2rp+1
    float2* F1b = g_F1 + ((size_t)b * NP + 2 * rp) * HH;
    F1b[k]       = E;
    F1b[HH + k]  = O;
}

// ---------------------------------------------------------------------------
// Kernel 3: column FFT (full complex 512-pt over the row axis), 8 columns per
// block via shared-memory transpose, then split into the 4 real planes.
__global__ void k_colfft() {
    __shared__ float2 s[8][NP];
    int k0 = blockIdx.x * 8;       // 32 column groups
    int b  = blockIdx.y;
    int t  = threadIdx.x;          // 256
    const float2* F1b = g_F1 + (size_t)b * NP * HH;
#pragma unroll
    for (int it = 0; it < 16; it++) {
        int idx = t + (it << 8);
        int r = idx >> 3, c = idx & 7;
        s[c][__brev(r) >> 23] = F1b[(size_t)r * HH + k0 + c];
    }
    __syncthreads();
#pragma unroll
    for (int st = 0; st < 9; st++) {
        int half = 1 << st;
        int pos  = t & (half - 1);
        int i0   = ((t >> st) << (st + 1)) | pos;
        int i1   = i0 + half;
        float2 w = g_tw[pos << (8 - st)];
#pragma unroll
        for (int c = 0; c < 8; c++) {
            float2 u = s[c][i0], v = s[c][i1];
            float2 wv = cmul(w, v);
            s[c][i0] = cadd(u, wv);
            s[c][i1] = csub(u, wv);
        }
        __syncthreads();
    }
    const size_t ps = (size_t)NB * HH * HH;
#pragma unroll
    for (int it = 0; it < 16; it++) {
        int idx = t + (it << 8);
        int r = idx >> 3, c = idx & 7;
        float2 v = s[c][r];
        int k = k0 + c;
        if (r < HH) {
            size_t o = ((size_t)b * HH + r) * HH + k;
            g_planes[o]          = v.x;   // low.real
            g_planes[ps + o]     = v.y;   // low.imag
        } else {
            size_t o = ((size_t)b * HH + (r - HH)) * HH + k;
            g_planes[2 * ps + o] = v.x;   // high.real
            g_planes[3 * ps + o] = v.y;   // high.imag
        }
    }
}

// ---------------------------------------------------------------------------
// Kernel 4: per-plane 3x3 conv + bias, cumprod over batch, 1x1 fuse,
// BN+SiLU, BN+ReLU, broadcast by w_final into (16,64,256,256).
// One block per output row (256 blocks), 128 threads, 2 pixels/thread (float2).
__global__ void k_final(const float* __restrict__ sw,  const float* __restrict__ sb,
                        const float* __restrict__ fw,  const float* __restrict__ fg,
                        const float* __restrict__ fb,  const float* __restrict__ gg,
                        const float* __restrict__ gb,  const float* __restrict__ wf,
                        float* __restrict__ out) {
    __shared__ float s_wf[64];
    __shared__ float s_w[9];
    int t = threadIdx.x;           // 128
    if (t < 64) s_wf[t] = wf[t];
    if (t >= 64 && t < 73) s_w[t - 64] = sw[t - 64];
    __syncthreads();

    int i = blockIdx.x;            // row 0..255
    int j = 2 * t;                 // cols j, j+1

    float sdib = sb[0];
    float fsc  = fg[0] * rsqrtf(1.0f + 1e-5f);
    float fbi  = fb[0];
    float gsc  = gg[0] * rsqrtf(1.0f + 1e-5f);
    float gbi  = gb[0];
    float fwv[4] = {fw[0], fw[1], fw[2], fw[3]};

    float pr[4][2];
#pragma unroll
    for (int p = 0; p < 4; p++) { pr[p][0] = 1.0f; pr[p][1] = 1.0f; }

    const size_t ps = (size_t)NB * HH * HH;

    for (int b = 0; b < NB; b++) {
        float acc0 = 0.0f, acc1 = 0.0f;
#pragma unroll
        for (int p = 0; p < 4; p++) {
            const float* Pb = g_planes + (size_t)p * ps + ((size_t)b * HH) * HH;
            float q[3][4];
#pragma unroll
            for (int dr = 0; dr < 3; dr++) {
                int ri = i + dr - 1;
                bool rv = ((unsigned)ri < (unsigned)HH);
#pragma unroll
                for (int dc = 0; dc < 4; dc++) {
                    int cj = j + dc - 1;
                    q[dr][dc] = (rv && (unsigned)cj < (unsigned)HH)
                                ? Pb[(size_t)ri * HH + cj] : 0.0f;
                }
            }
            float c0 = sdib, c1 = sdib;
#pragma unroll
            for (int dr = 0; dr < 3; dr++)
#pragma unroll
                for (int dc = 0; dc < 3; dc++) {
                    float wv = s_w[dr * 3 + dc];
                    c0 = fmaf(wv, q[dr][dc],     c0);
                    c1 = fmaf(wv, q[dr][dc + 1], c1);
                }
            pr[p][0] *= c0;
            pr[p][1] *= c1;
            acc0 = fmaf(fwv[p], pr[p][0], acc0);
            acc1 = fmaf(fwv[p], pr[p][1], acc1);
        }
        float u0 = fsc * acc0 + fbi;  u0 = u0 / (1.0f + expf(-u0));
        float u1 = fsc * acc1 + fbi;  u1 = u1 / (1.0f + expf(-u1));
        float v0 = fmaxf(gsc * u0 + gbi, 0.0f);
        float v1 = fmaxf(gsc * u1 + gbi, 0.0f);

        float* ob = out + ((((size_t)b * 64) * HH + i) * HH + j);
#pragma unroll
        for (int o = 0; o < 64; o++) {
            float w = s_wf[o];
            *(float2*)(ob + (size_t)o * HH * HH) = make_float2(w * v0, w * v1);
        }
    }
}

// ---------------------------------------------------------------------------
extern "C" void kernel_launch(void* const* d_in, const int* in_sizes, int n_in,
                              void* d_out, int out_size) {
    const float* x       = (const float*)d_in[0];
    // gw branch (indices 1..8) is numerically dead: softmax over singleton axis == 1.
    const float* w_spd   = (const float*)d_in[9];
    const float* bn_g    = (const float*)d_in[10];
    const float* bn_b    = (const float*)d_in[11];
    const float* sdi_w   = (const float*)d_in[12];
    const float* sdi_b   = (const float*)d_in[13];
    const float* fuse_w  = (const float*)d_in[14];
    const float* fuse_g  = (const float*)d_in[15];
    const float* fuse_b  = (const float*)d_in[16];
    const float* gen_g   = (const float*)d_in[17];
    const float* gen_b   = (const float*)d_in[18];
    const float* w_final = (const float*)d_in[19];
    float* out = (float*)d_out;

    k_twiddle<<<1, 256>>>();

    dim3 g1(NP, NB);
    k_spd<<<g1, 256>>>(x, w_spd, bn_g, bn_b);

    dim3 g2(HH, NB);       // 256 row pairs x 16 batches
    k_rowfft<<<g2, 256>>>();

    dim3 g3(32, NB);       // 32 column groups x 16 batches
    k_colfft<<<g3, 256>>>();

    k_final<<<HH, 128>>>(sdi_w, sdi_b, fuse_w, fuse_g, fuse_b,
                         gen_g, gen_b, w_final, out);
}